// round 17
// baseline (speedup 1.0000x reference)
#include <cuda_runtime.h>
#include <cstdint>

#define DEVINL __device__ __forceinline__

static constexpr int B_ = 32, N_ = 256, T_ = 1024, O_ = 1024, G_ = 8;

// Scratch: w_bot in swizzled 128x32 tiles (128 MB) + x re-tiled (32 MB).
__device__ float g_wbot[(size_t)B_ * O_ * T_];
__device__ float g_xt[(size_t)B_ * N_ * T_];

// ---------------- helpers ----------------
DEVINL uint32_t smem_u32(const void* p) {
    uint32_t a;
    asm("{ .reg .u64 t; cvta.to.shared.u64 t, %1; cvt.u32.u64 %0, t; }" : "=r"(a) : "l"(p));
    return a;
}
DEVINL uint32_t tf32_rna_bits(float x) {
    uint32_t u;
    asm("cvt.rna.tf32.f32 %0, %1;" : "=r"(u) : "f"(x));
    return u;
}
DEVINL void ldsm_x4(uint32_t& r0, uint32_t& r1, uint32_t& r2, uint32_t& r3,
                    uint32_t addr) {
    asm volatile("ldmatrix.sync.aligned.m8n8.x4.shared.b16 {%0,%1,%2,%3}, [%4];"
                 : "=r"(r0), "=r"(r1), "=r"(r2), "=r"(r3) : "r"(addr));
}
DEVINL void mma_tf32(float& c0, float& c1, float& c2, float& c3,
                     uint32_t a0, uint32_t a1, uint32_t a2, uint32_t a3,
                     uint32_t b0, uint32_t b1) {
    asm volatile(
        "mma.sync.aligned.m16n8k8.row.col.f32.tf32.tf32.f32 "
        "{%0,%1,%2,%3}, {%4,%5,%6,%7}, {%8,%9}, {%0,%1,%2,%3};"
        : "+f"(c0), "+f"(c1), "+f"(c2), "+f"(c3)
        : "r"(a0), "r"(a1), "r"(a2), "r"(a3), "r"(b0), "r"(b1));
}
DEVINL void mbar_init(uint32_t a, uint32_t c) {
    asm volatile("mbarrier.init.shared.b64 [%0], %1;" :: "r"(a), "r"(c) : "memory");
}
DEVINL void mbar_expect_tx(uint32_t a, uint32_t tx) {
    asm volatile("mbarrier.arrive.expect_tx.shared.b64 _, [%0], %1;"
                 :: "r"(a), "r"(tx) : "memory");
}
DEVINL void mbar_wait(uint32_t a, uint32_t parity) {
    asm volatile(
        "{\n\t.reg .pred P;\n\t"
        "WL_%=:\n\t"
        "mbarrier.try_wait.parity.acquire.cta.shared::cta.b64 P, [%0], %1, 0x989680;\n\t"
        "@P bra.uni WD_%=;\n\t"
        "bra.uni WL_%=;\n\t"
        "WD_%=:\n\t}"
        :: "r"(a), "r"(parity) : "memory");
}
// Bulk async copy gmem->smem, mbarrier transaction completion (sm_90+).
DEVINL void bulk_g2s(uint32_t dst, const void* src, uint32_t bytes, uint32_t mbar) {
    asm volatile(
        "cp.async.bulk.shared::cta.global.mbarrier::complete_tx::bytes [%0], [%1], %2, [%3];"
        :: "r"(dst), "l"(src), "r"(bytes), "r"(mbar) : "memory");
}
DEVINL void fence_async_shared() { asm volatile("fence.proxy.async.shared::cta;" ::: "memory"); }

// Tile layout: [128 rows r][32 cols c] floats, 16 KB contiguous, with XOR
// swizzle: float4-granule g = (c>>2) stored at granule (g ^ (r&7)) within the
// row. Makes ldmatrix 8-row phases bank-conflict-free without padding.
DEVINL uint32_t tile_f4_off(int r, int c) {
    return (uint32_t)(r * 32 + ((((c >> 2) & 7) ^ (r & 7)) << 2));
}

// ---------------- Pass 0+1 fused: x re-tile + genre mixing ----------------
// Blocks [0,1024): mix -> g_wbot tiles.  Blocks [1024,9216): x -> g_xt tiles.
static constexpr int MIX_BLOCKS = (O_ * T_ / 4) / 256;           // 1024
static constexpr int XT_BLOCKS = (B_ * N_ * T_ / 4) / 256;       // 8192

__global__ void __launch_bounds__(256) prep_kernel(const float* __restrict__ x,
                                                   const float* __restrict__ y,
                                                   const float* __restrict__ weight,
                                                   const float* __restrict__ mask) {
    const int tid = threadIdx.x;
    if (blockIdx.x >= MIX_BLOCKS) {
        // ---- x re-tile: g_xt tile = (b*2 + (m>>7))*32 + (t>>5) ----
        const int idx = (blockIdx.x - MIX_BLOCKS) * 256 + tid;   // over B*N*T/4
        const float4 v = reinterpret_cast<const float4*>(x)[idx];
        const int b = idx >> 16;            // N*T/4 = 65536
        const int rem = idx & 65535;
        const int m = rem >> 8;             // T/4 = 256 groups per row
        const int t = (rem & 255) << 2;
        const int tile = (b * 2 + (m >> 7)) * 32 + (t >> 5);
        float* dst = g_xt + (size_t)tile * 4096 + tile_f4_off(m & 127, t & 31);
        *reinterpret_cast<float4*>(dst) = v;
        return;
    }
    // ---- mix: w_bot[b,o,t] = sum_g y[b,g]*weight[g,o,t]*mask[o,t] ----
    __shared__ float ys[B_ * G_];
    ys[tid] = y[tid];
    __syncthreads();

    const int idx = blockIdx.x * 256 + tid;  // over O*T/4
    const int o = idx >> 8;
    const int t = (idx & 255) << 2;
    const float4 mv = reinterpret_cast<const float4*>(mask)[idx];
    float4 wm[G_];
#pragma unroll
    for (int g = 0; g < G_; g++) {
        float4 w = reinterpret_cast<const float4*>(weight)[(size_t)g * (O_ * T_ / 4) + idx];
        wm[g].x = w.x * mv.x; wm[g].y = w.y * mv.y;
        wm[g].z = w.z * mv.z; wm[g].w = w.w * mv.w;
    }
    const uint32_t inoff = tile_f4_off(o & 127, t & 31);
    const int tsub = (o >> 7) * 32 + (t >> 5);   // tile within batch slice
#pragma unroll 4
    for (int b = 0; b < B_; b++) {
        float4 a = make_float4(0.f, 0.f, 0.f, 0.f);
#pragma unroll
        for (int g = 0; g < G_; g++) {
            const float yv = ys[b * G_ + g];
            a.x = fmaf(yv, wm[g].x, a.x);
            a.y = fmaf(yv, wm[g].y, a.y);
            a.z = fmaf(yv, wm[g].z, a.z);
            a.w = fmaf(yv, wm[g].w, a.w);
        }
        a.x = __uint_as_float(tf32_rna_bits(a.x));
        a.y = __uint_as_float(tf32_rna_bits(a.y));
        a.z = __uint_as_float(tf32_rna_bits(a.z));
        a.w = __uint_as_float(tf32_rna_bits(a.w));
        float* dst = g_wbot + (size_t)(b * 256 + tsub) * 4096 + inoff;
        *reinterpret_cast<float4*>(dst) = a;
    }
}

// ---------------- Pass 2: batched tf32 GEMM, bulk-copy pipeline ----------
// out[b, m, o] = sum_t x[b,m,t] * w_bot[b,o,t] + bias[o]
// CTA tile 128x128x32, 4 warps (64x64 warp tile), 3 stages, 2 CTAs/SM.
// Stage fill = 2 x cp.async.bulk; refills issued BEFORE the MMA block;
// fragments double-buffered across kk (LDSM kk+1 under MMAs of kk).
static constexpr int BK = 32, STAGES = 3, NKT = T_ / BK;
static constexpr uint32_t STAGE_BYTES = 32768;           // A 16K + B 16K
static constexpr uint32_t MB_OFF = STAGES * STAGE_BYTES; // 98304
static constexpr uint32_t SMEM_BYTES = MB_OFF + 64;

__global__ void __launch_bounds__(128, 2)
gemm_kernel(const float* __restrict__ bias, float* __restrict__ out) {
    extern __shared__ float smem[];
    const uint32_t sbase = smem_u32(smem);
    const int tid = threadIdx.x;
    const int lane = tid & 31, wid = tid >> 5;
    const int lq = lane >> 2, lr = lane & 3;
    const int wm = wid & 1, wn = wid >> 1;
    const int b = blockIdx.z;
    const int ot = blockIdx.x;           // o-tile (128)
    const int mt = blockIdx.y;           // m-tile (128)

    const float* gA = g_xt + (size_t)((b * 2 + mt) * 32) * 4096;
    const float* gB = g_wbot + (size_t)((b * 8 + ot) * 32) * 4096;

    const int m_base = wm * 64;
    const int n_base = wn * 64;

    // Per-lane LDSM source addresses (byte offsets within a tile), swizzled.
    const int aR = m_base + ((lane >> 3) & 1) * 8 + (lane & 7);
    const int ag0 = lane >> 4;
    const int bR = n_base + (lane >> 4) * 8 + (lane & 7);
    const int bg0 = (lane >> 3) & 1;
    uint32_t aOffkk[4], bOffkk[4];
#pragma unroll
    for (int kk = 0; kk < 4; kk++) {
        aOffkk[kk] = (uint32_t)(aR * 128 + (((ag0 + 2 * kk) ^ (aR & 7)) << 4));
        bOffkk[kk] = 16384u + (uint32_t)(bR * 128 + (((bg0 + 2 * kk) ^ (bR & 7)) << 4));
    }

    float acc[4][8][4];
#pragma unroll
    for (int i = 0; i < 4; i++)
#pragma unroll
        for (int j = 0; j < 8; j++)
#pragma unroll
            for (int k = 0; k < 4; k++) acc[i][j][k] = 0.f;

    // mbarrier init + prologue fills (tiles 0..2)
    if (tid == 0) {
        for (int s = 0; s < STAGES; s++) mbar_init(MB_OFF + sbase + 8 * s, 1);
    }
    __syncthreads();
    if (tid == 0) {
#pragma unroll
        for (int s = 0; s < STAGES; s++) {
            const uint32_t mb = sbase + MB_OFF + 8 * s;
            mbar_expect_tx(mb, STAGE_BYTES);
            bulk_g2s(sbase + s * STAGE_BYTES, gA + (size_t)s * 4096, 16384, mb);
            bulk_g2s(sbase + s * STAGE_BYTES + 16384, gB + (size_t)s * 4096, 16384, mb);
        }
    }

    uint32_t afr[2][4][4];   // double-buffered A fragments
    uint32_t bfr[2][8][2];   // double-buffered B fragments

    for (int kt = 0; kt < NKT; kt++) {
        const int s = kt % STAGES;
        mbar_wait(sbase + MB_OFF + 8 * s, (uint32_t)((kt / STAGES) & 1));
        __syncthreads();  // all threads past kt-1's reads; stage (kt-1)%3 free

        // Refill freed stage with tile kt+2 BEFORE compute (max overlap).
        if (tid == 0 && kt >= 1 && kt + 2 < NKT) {
            fence_async_shared();
            const int kn = kt + 2;
            const int sf = kn % STAGES;  // == (kt-1)%STAGES
            const uint32_t mbf = sbase + MB_OFF + 8 * sf;
            const uint32_t stf = sbase + (uint32_t)sf * STAGE_BYTES;
            mbar_expect_tx(mbf, STAGE_BYTES);
            bulk_g2s(stf, gA + (size_t)kn * 4096, 16384, mbf);
            bulk_g2s(stf + 16384, gB + (size_t)kn * 4096, 16384, mbf);
        }

        const uint32_t stg = sbase + (uint32_t)s * STAGE_BYTES;

        // Prefetch kk=0 fragments
#pragma unroll
        for (int mf = 0; mf < 4; mf++)
            ldsm_x4(afr[0][mf][0], afr[0][mf][1], afr[0][mf][2], afr[0][mf][3],
                    stg + aOffkk[0] + (uint32_t)(mf * 2048));
#pragma unroll
        for (int nfp = 0; nfp < 4; nfp++)
            ldsm_x4(bfr[0][2 * nfp][0], bfr[0][2 * nfp][1],
                    bfr[0][2 * nfp + 1][0], bfr[0][2 * nfp + 1][1],
                    stg + bOffkk[0] + (uint32_t)(nfp * 2048));

#pragma unroll
        for (int kk = 0; kk < 4; kk++) {
            const int cur = kk & 1, nxt = cur ^ 1;
            if (kk < 3) {  // prefetch kk+1 fragments under this kk's MMAs
#pragma unroll
                for (int mf = 0; mf < 4; mf++)
                    ldsm_x4(afr[nxt][mf][0], afr[nxt][mf][1],
                            afr[nxt][mf][2], afr[nxt][mf][3],
                            stg + aOffkk[kk + 1] + (uint32_t)(mf * 2048));
#pragma unroll
                for (int nfp = 0; nfp < 4; nfp++)
                    ldsm_x4(bfr[nxt][2 * nfp][0], bfr[nxt][2 * nfp][1],
                            bfr[nxt][2 * nfp + 1][0], bfr[nxt][2 * nfp + 1][1],
                            stg + bOffkk[kk + 1] + (uint32_t)(nfp * 2048));
            }
#pragma unroll
            for (int mf = 0; mf < 4; mf++)
#pragma unroll
                for (int nf = 0; nf < 8; nf++)
                    mma_tf32(acc[mf][nf][0], acc[mf][nf][1],
                             acc[mf][nf][2], acc[mf][nf][3],
                             afr[cur][mf][0], afr[cur][mf][1],
                             afr[cur][mf][2], afr[cur][mf][3],
                             bfr[cur][nf][0], bfr[cur][nf][1]);
        }
    }

    // Epilogue: registers -> global with bias (float2 stores).
    float* outp = out + ((size_t)b * N_ + mt * 128 + m_base) * O_ + ot * 128 + n_base;
    const float* bp = bias + ot * 128 + n_base;
#pragma unroll
    for (int nf = 0; nf < 8; nf++) {
        const int col = nf * 8 + lr * 2;
        const float bv0 = __ldg(bp + col);
        const float bv1 = __ldg(bp + col + 1);
#pragma unroll
        for (int mf = 0; mf < 4; mf++) {
            const int r = mf * 16 + lq;
            float2 v0 = make_float2(acc[mf][nf][0] + bv0, acc[mf][nf][1] + bv1);
            float2 v1 = make_float2(acc[mf][nf][2] + bv0, acc[mf][nf][3] + bv1);
            *reinterpret_cast<float2*>(outp + (size_t)r * O_ + col) = v0;
            *reinterpret_cast<float2*>(outp + (size_t)(r + 8) * O_ + col) = v1;
        }
    }
}

// ---------------- launch ----------------
extern "C" void kernel_launch(void* const* d_in, const int* in_sizes, int n_in,
                              void* d_out, int out_size) {
    const float* x      = (const float*)d_in[0];  // [B,N,T]
    const float* y      = (const float*)d_in[1];  // [B,G]
    const float* weight = (const float*)d_in[2];  // [G,O,T]
    const float* mask   = (const float*)d_in[3];  // [O,T]
    const float* bias   = (const float*)d_in[4];  // [O]
    float* out = (float*)d_out;                   // [B,N,O]

    prep_kernel<<<MIX_BLOCKS + XT_BLOCKS, 256>>>(x, y, weight, mask);

    cudaFuncSetAttribute(gemm_kernel, cudaFuncAttributeMaxDynamicSharedMemorySize,
                         SMEM_BYTES);
    dim3 grid(O_ / 128, N_ / 128, B_);
    gemm_kernel<<<grid, 128, SMEM_BYTES>>>(bias, out);
}